// round 9
// baseline (speedup 1.0000x reference)
#include <cuda_runtime.h>
#include <cstdint>

#define BB 64
#define SS 196
#define HALFS 98
#define OO 10
#define SLAB 4096            // float2 per 64x64 slab
#define NT 128               // 4 worker warps, no TMA warp

__device__ __align__(128) float2 g_coresT[SS * SLAB];
__device__ float g_vecL[BB][64];
__device__ float g_vecR[BB][64];

// ---------------------------------------------------------------------------
// Kernel 1: transpose right-half slabs, 4 CTAs per slab (16-row strips).
// ---------------------------------------------------------------------------
__global__ __launch_bounds__(128) void transpose_kernel(const float2* __restrict__ cores)
{
    __shared__ float2 tile[16][65];
    const int s  = (blockIdx.x >> 2) + HALFS;
    const int lb = (blockIdx.x & 3) * 16;
    const float2* src = cores + (size_t)s * SLAB + (size_t)lb * 64;
    float2* dst = g_coresT + (size_t)s * SLAB + lb;
    const int t = threadIdx.x;

    float2 v[8];
#pragma unroll
    for (int i = 0; i < 8; i++) v[i] = src[t + i * 128];
#pragma unroll
    for (int i = 0; i < 8; i++) {
        int idx = t + i * 128;
        tile[idx >> 6][idx & 63] = v[i];
    }
    __syncthreads();
#pragma unroll
    for (int i = 0; i < 8; i++) {
        int idx = t + i * 128;
        v[i] = tile[idx & 15][idx >> 4];
    }
#pragma unroll
    for (int i = 0; i < 8; i++) {
        int idx = t + i * 128;
        dst[(idx >> 4) * 64 + (idx & 15)] = v[i];
    }
}

// ---------------------------------------------------------------------------
// Kernel 2: 64 CTAs x 128 threads (4 worker warps, NO staging).
// Warp w, lane = (g = m-half, c): column n = w*16 + c, m in [g*32, g*32+32).
// C for step k+1 streams L2 -> registers (32 LDG.64/thread, double-buffered)
// while step k's 128 FMAs run. lv via broadcast LDS.128. One sync per step.
// Combine: x-fold before a single shfl.bfly(16) per batch.
// ---------------------------------------------------------------------------
__global__ __launch_bounds__(NT, 1) void chain_kernel(const float* __restrict__ x,
                                                      const float2* __restrict__ cores)
{
    __shared__ float lvsm[288];        // lv0[2][72] @0, lv1[2][72] @144
    __shared__ float2 xsh[2][HALFS];

    const int t    = threadIdx.x;
    const int w    = t >> 5;
    const int lane = t & 31;
    const int g    = lane >> 4;
    const int c    = lane & 15;
    const int half = blockIdx.x >> 5;
    const int b0   = (blockIdx.x & 31) * 2;

    const float2* s0 = half ? (g_coresT + (size_t)(SS - 1) * SLAB) : cores;
    const long sstride = half ? -(long)SLAB : (long)SLAB;

    // stage x in iteration order
    const float2* xf = (const float2*)x;        // [B][S]
    for (int k = t; k < HALFS; k += NT) {
        int s = half ? (SS - 1 - k) : k;
        xsh[0][k] = xf[(b0 + 0) * SS + s];
        xsh[1][k] = xf[(b0 + 1) * SS + s];
    }
    // init lv buf0 (padded layout: half h at offset h*36)
    if (t < 64) {
        int h = t >> 5, p = t & 31;
        float v = (t == 0) ? 1.f : 0.f;
        lvsm[h * 36 + p]       = v;   // batch0, buf0
        lvsm[144 + h * 36 + p] = v;   // batch1, buf0
    }

    const int n    = w * 16 + c;
    const int coff = g * 2048 + n;                 // float2 offset of (m=g*32, n)
    const int hh   = w >> 1;
    const int sto  = hh * 36 + (w & 1) * 16 + c;   // lv store offset for column n
    const bool wr  = (g == 0);

    // prologue: slab 0 into A
    float2 A[32], B[32];
    {
        const float2* p0 = s0 + coff;
#pragma unroll
        for (int i = 0; i < 32; i++) A[i] = __ldg(p0 + i * 64);
    }
    const float2* pnext = s0 + sstride + coff;     // slab k+1 source

    __syncthreads();

#define WSTEP(CUR, NXT, K, PAR)                                              \
    {                                                                        \
        /* stream slab K+1 from L2 while FMAs run */                         \
        if ((K) < HALFS - 1) {                                               \
            _Pragma("unroll")                                                \
            for (int i = 0; i < 32; i++) NXT[i] = __ldg(pnext + i * 64);     \
            pnext += sstride;                                                \
        }                                                                    \
        /* ---------- batch 0 ---------- */                                  \
        {                                                                    \
            const float4* lv4 = (const float4*)(lvsm + (PAR) * 72 + g * 36); \
            float4 L[8];                                                     \
            _Pragma("unroll")                                                \
            for (int q = 0; q < 8; q++) L[q] = lv4[q];                       \
            float sx0 = 0.f, sx1 = 0.f, sy0 = 0.f, sy1 = 0.f;                \
            _Pragma("unroll")                                                \
            for (int q = 0; q < 8; q++) {                                    \
                float2 c0 = CUR[4*q+0], c1 = CUR[4*q+1];                     \
                float2 c2 = CUR[4*q+2], c3 = CUR[4*q+3];                     \
                sx0 = fmaf(L[q].x, c0.x, sx0); sy0 = fmaf(L[q].x, c0.y, sy0);\
                sx1 = fmaf(L[q].y, c1.x, sx1); sy1 = fmaf(L[q].y, c1.y, sy1);\
                sx0 = fmaf(L[q].z, c2.x, sx0); sy0 = fmaf(L[q].z, c2.y, sy0);\
                sx1 = fmaf(L[q].w, c3.x, sx1); sy1 = fmaf(L[q].w, c3.y, sy1);\
            }                                                                \
            float2 xk = xsh[0][(K)];                                         \
            float part = fmaf(xk.x, sx0 + sx1, xk.y * (sy0 + sy1));          \
            float oth  = __shfl_xor_sync(0xffffffffu, part, 16);             \
            if (wr) lvsm[((PAR) ^ 1) * 72 + sto] = part + oth;               \
        }                                                                    \
        /* ---------- batch 1 ---------- */                                  \
        {                                                                    \
            const float4* lv4 = (const float4*)(lvsm + 144 + (PAR) * 72 + g * 36); \
            float4 L[8];                                                     \
            _Pragma("unroll")                                                \
            for (int q = 0; q < 8; q++) L[q] = lv4[q];                       \
            float sx0 = 0.f, sx1 = 0.f, sy0 = 0.f, sy1 = 0.f;                \
            _Pragma("unroll")                                                \
            for (int q = 0; q < 8; q++) {                                    \
                float2 c0 = CUR[4*q+0], c1 = CUR[4*q+1];                     \
                float2 c2 = CUR[4*q+2], c3 = CUR[4*q+3];                     \
                sx0 = fmaf(L[q].x, c0.x, sx0); sy0 = fmaf(L[q].x, c0.y, sy0);\
                sx1 = fmaf(L[q].y, c1.x, sx1); sy1 = fmaf(L[q].y, c1.y, sy1);\
                sx0 = fmaf(L[q].z, c2.x, sx0); sy0 = fmaf(L[q].z, c2.y, sy0);\
                sx1 = fmaf(L[q].w, c3.x, sx1); sy1 = fmaf(L[q].w, c3.y, sy1);\
            }                                                                \
            float2 xk = xsh[1][(K)];                                         \
            float part = fmaf(xk.x, sx0 + sx1, xk.y * (sy0 + sy1));          \
            float oth  = __shfl_xor_sync(0xffffffffu, part, 16);             \
            if (wr) lvsm[144 + ((PAR) ^ 1) * 72 + sto] = part + oth;         \
        }                                                                    \
        __syncthreads();                                                     \
    }

#pragma unroll 1
    for (int k = 0; k < HALFS; k += 2) {
        WSTEP(A, B, k, 0);
        WSTEP(B, A, k + 1, 1);
    }
#undef WSTEP

    if (t < 64) {            // final lv in buffer 0 (98 even)
        int h = t >> 5, p = t & 31;
        float v0 = lvsm[h * 36 + p];
        float v1 = lvsm[144 + h * 36 + p];
        if (half == 0) { g_vecL[b0][t] = v0; g_vecL[b0 + 1][t] = v1; }
        else           { g_vecR[b0][t] = v0; g_vecR[b0 + 1][t] = v1; }
    }
}

// ---------------------------------------------------------------------------
// Kernel 3: out[b,o] = sum_{l,r} L[b,l] * oc[o,l,r] * R[b,r]
// ---------------------------------------------------------------------------
__global__ __launch_bounds__(64) void out_kernel(const float* __restrict__ oc,
                                                 float* __restrict__ out)
{
    const int b = blockIdx.x;
    const int r = threadIdx.x;
    __shared__ float Ls[64];
    __shared__ float red[2][OO];

    Ls[r] = g_vecL[b][r];
    const float R = g_vecR[b][r];
    __syncthreads();

    for (int o = 0; o < OO; o++) {
        float acc = 0.f;
        const float* m = oc + o * 4096 + r;
#pragma unroll 8
        for (int l = 0; l < 64; l++) acc = fmaf(Ls[l], m[l * 64], acc);
        acc *= R;
#pragma unroll
        for (int off = 16; off; off >>= 1)
            acc += __shfl_down_sync(0xffffffffu, acc, off);
        if ((r & 31) == 0) red[r >> 5][o] = acc;
    }
    __syncthreads();
    if (r < OO) out[b * OO + r] = red[0][r] + red[1][r];
}

// ---------------------------------------------------------------------------
extern "C" void kernel_launch(void* const* d_in, const int* in_sizes, int n_in,
                              void* d_out, int out_size)
{
    const float* x = nullptr;
    const float* cores = nullptr;
    const float* oc = nullptr;
    for (int i = 0; i < n_in; i++) {
        if (in_sizes[i] == BB * SS * 2)         x = (const float*)d_in[i];
        else if (in_sizes[i] == SS * SLAB * 2)  cores = (const float*)d_in[i];
        else if (in_sizes[i] == OO * 4096)      oc = (const float*)d_in[i];
    }

    transpose_kernel<<<4 * (SS - HALFS), 128>>>((const float2*)cores);
    chain_kernel<<<64, NT>>>(x, (const float2*)cores);
    out_kernel<<<BB, 64>>>(oc, (float*)d_out);
}

// round 10
// speedup vs baseline: 1.7986x; 1.7986x over previous
#include <cuda_runtime.h>
#include <cstdint>

#define BB 64
#define SS 196
#define HALFS 98
#define OO 10
#define SLAB 4096            // float2 per 64x64 slab
#define SLAB_BYTES 32768
#define RING 6
#define NT 160               // 4 worker warps + 1 TMA warp

__device__ __align__(128) float2 g_coresT[SS * SLAB];
__device__ float g_vecL[BB][64];
__device__ float g_vecR[BB][64];

// ---------------------------------------------------------------------------
__device__ __forceinline__ uint32_t smem_u32(const void* p) {
    uint32_t a;
    asm("{ .reg .u64 t; cvta.to.shared.u64 t, %1; cvt.u32.u64 %0, t; }"
        : "=r"(a) : "l"(p));
    return a;
}
__device__ __forceinline__ void mbar_init(uint32_t a, uint32_t cnt) {
    asm volatile("mbarrier.init.shared.b64 [%0], %1;" :: "r"(a), "r"(cnt) : "memory");
}
__device__ __forceinline__ void mbar_expect_tx(uint32_t a, uint32_t bytes) {
    asm volatile("mbarrier.arrive.expect_tx.shared.b64 _, [%0], %1;"
                 :: "r"(a), "r"(bytes) : "memory");
}
__device__ __forceinline__ void mbar_wait(uint32_t a, uint32_t phase) {
    asm volatile(
        "{\n\t.reg .pred P;\n\t"
        "W_%=:\n\t"
        "mbarrier.try_wait.parity.shared.b64 P, [%0], %1;\n\t"
        "@!P bra W_%=;\n\t}"
        :: "r"(a), "r"(phase) : "memory");
}
__device__ __forceinline__ void bulk_g2s(uint32_t dst, const void* src,
                                         uint32_t bytes, uint32_t mbar) {
    asm volatile(
        "cp.async.bulk.shared::cluster.global.mbarrier::complete_tx::bytes "
        "[%0], [%1], %2, [%3];"
        :: "r"(dst), "l"(src), "r"(bytes), "r"(mbar) : "memory");
}

// ---------------------------------------------------------------------------
// Kernel 1: transpose right-half slabs, 4 CTAs per slab (16-row strips).
// ---------------------------------------------------------------------------
__global__ __launch_bounds__(128) void transpose_kernel(const float2* __restrict__ cores)
{
    __shared__ float2 tile[16][65];
    const int s  = (blockIdx.x >> 2) + HALFS;
    const int lb = (blockIdx.x & 3) * 16;
    const float2* src = cores + (size_t)s * SLAB + (size_t)lb * 64;
    float2* dst = g_coresT + (size_t)s * SLAB + lb;
    const int t = threadIdx.x;

    float2 v[8];
#pragma unroll
    for (int i = 0; i < 8; i++) v[i] = src[t + i * 128];
#pragma unroll
    for (int i = 0; i < 8; i++) {
        int idx = t + i * 128;
        tile[idx >> 6][idx & 63] = v[i];
    }
    __syncthreads();
#pragma unroll
    for (int i = 0; i < 8; i++) {
        int idx = t + i * 128;
        v[i] = tile[idx & 15][idx >> 4];
    }
#pragma unroll
    for (int i = 0; i < 8; i++) {
        int idx = t + i * 128;
        dst[(idx >> 4) * 64 + (idx & 15)] = v[i];
    }
}

// ---------------------------------------------------------------------------
// Kernel 2: 64 CTAs x 160 threads (4 worker warps + 1 TMA warp).
// Worker warp w: lane = (g = m-half, c), column n = w*16 + c.
// Per step: b0 FMA -> [b1 lv preload] -> b0 fold/shfl/STS -> b1 FMA/fold/shfl/STS
// -> C prefetch (hides sync skew) -> one __syncthreads.
// TMA warp certifies slab k+2 pre-sync, refills slot k%RING post-sync.
// ---------------------------------------------------------------------------
__global__ __launch_bounds__(NT, 1) void chain_kernel(const float* __restrict__ x,
                                                      const float2* __restrict__ cores)
{
    extern __shared__ __align__(128) unsigned char dynsm[];
    float2* ring  = (float2*)dynsm;                               // 6 x 32KB
    float*  lvsm  = (float*)(dynsm + RING * SLAB_BYTES);          // lv0[2][72], lv1[2][72]
    float2* xsh   = (float2*)(dynsm + RING * SLAB_BYTES + 1152);  // [2][98]
    uint64_t* mbp = (uint64_t*)(dynsm + RING * SLAB_BYTES + 1152 + 1568);

    const uint32_t fb = smem_u32(mbp);
    const uint32_t ru = smem_u32(dynsm);

    const int t    = threadIdx.x;
    const int w    = t >> 5;
    const int lane = t & 31;
    const int g    = lane >> 4;
    const int half = blockIdx.x >> 5;
    const int b0   = (blockIdx.x & 31) * 2;

    const float2* s0 = half ? (g_coresT + (size_t)(SS - 1) * SLAB) : cores;
    const long sstride = half ? -(long)SLAB : (long)SLAB;

    // stage x in iteration order
    const float2* xf = (const float2*)x;        // [B][S]
    for (int k = t; k < HALFS; k += NT) {
        int s = half ? (SS - 1 - k) : k;
        xsh[k]         = xf[(b0 + 0) * SS + s];
        xsh[HALFS + k] = xf[(b0 + 1) * SS + s];
    }
    // init lv buf0 (padded layout: half h at offset h*36)
    if (t < 64) {
        int h = t >> 5, p = t & 31;
        float v = (t == 0) ? 1.f : 0.f;
        lvsm[h * 36 + p]       = v;   // batch0, buf0
        lvsm[144 + h * 36 + p] = v;   // batch1, buf0
    }
    if (t == 0)
        for (int j = 0; j < RING; j++) mbar_init(fb + 8 * j, 1);
    __syncthreads();

    if (w == 4 && lane == 0) {            // prologue: slabs 0..5
        for (int s = 0; s < RING; s++) {
            mbar_expect_tx(fb + 8 * s, SLAB_BYTES);
            bulk_g2s(ru + s * SLAB_BYTES, s0 + (long)s * sstride,
                     SLAB_BYTES, fb + 8 * s);
        }
        mbar_wait(fb + 0, 0);             // slab 0 (reg load)
        mbar_wait(fb + 8, 0);             // slab 1 (step-0 prefetch)
    }
    __syncthreads();

    if (w < 4) {
        // ============================ workers ============================
        const int c  = lane & 15;
        const int n  = w * 16 + c;
        const int coff = g * 2048 + n;    // float2 offset of (m = g*32, n)
        const int hh = w >> 1;            // n >> 5
        const int sto = hh * 36 + (w & 1) * 16 + c;   // lv store offset
        const bool wr = (g == 0);

        float2 A[32], B[32];
        {
            const float2* P = ring + coff;
#pragma unroll
            for (int i = 0; i < 32; i++) A[i] = P[i * 64];
        }
        int slotn = 1;                    // ring slot of slab k+1

#define WSTEP(CUR, NXT, K, PAR)                                              \
        {                                                                    \
            /* ---------- batch 0: accumulate ---------- */                  \
            float p0;                                                        \
            {                                                                \
                const float4* lv4 = (const float4*)(lvsm + (PAR) * 72 + g * 36); \
                float4 L[8];                                                 \
                _Pragma("unroll")                                            \
                for (int q = 0; q < 8; q++) L[q] = lv4[q];                   \
                float sx0 = 0.f, sx1 = 0.f, sy0 = 0.f, sy1 = 0.f;            \
                _Pragma("unroll")                                            \
                for (int q = 0; q < 8; q++) {                                \
                    float2 c0 = CUR[4*q+0], c1 = CUR[4*q+1];                 \
                    float2 c2 = CUR[4*q+2], c3 = CUR[4*q+3];                 \
                    sx0 = fmaf(L[q].x, c0.x, sx0); sy0 = fmaf(L[q].x, c0.y, sy0); \
                    sx1 = fmaf(L[q].y, c1.x, sx1); sy1 = fmaf(L[q].y, c1.y, sy1); \
                    sx0 = fmaf(L[q].z, c2.x, sx0); sy0 = fmaf(L[q].z, c2.y, sy0); \
                    sx1 = fmaf(L[q].w, c3.x, sx1); sy1 = fmaf(L[q].w, c3.y, sy1); \
                }                                                            \
                float2 xk = xsh[(K)];                                        \
                p0 = fmaf(xk.x, sx0 + sx1, xk.y * (sy0 + sy1));              \
            }                                                                \
            /* ---------- batch 1 lv preload (latency under b0 tail) ----- */\
            float4 M[8];                                                     \
            {                                                                \
                const float4* lv4 = (const float4*)(lvsm + 144 + (PAR) * 72 + g * 36); \
                _Pragma("unroll")                                            \
                for (int q = 0; q < 8; q++) M[q] = lv4[q];                   \
            }                                                                \
            /* ---------- batch 0 tail ---------- */                         \
            {                                                                \
                float oth = __shfl_xor_sync(0xffffffffu, p0, 16);            \
                if (wr) lvsm[((PAR) ^ 1) * 72 + sto] = p0 + oth;             \
            }                                                                \
            /* ---------- batch 1 ---------- */                              \
            {                                                                \
                float sx0 = 0.f, sx1 = 0.f, sy0 = 0.f, sy1 = 0.f;            \
                _Pragma("unroll")                                            \
                for (int q = 0; q < 8; q++) {                                \
                    float2 c0 = CUR[4*q+0], c1 = CUR[4*q+1];                 \
                    float2 c2 = CUR[4*q+2], c3 = CUR[4*q+3];                 \
                    sx0 = fmaf(M[q].x, c0.x, sx0); sy0 = fmaf(M[q].x, c0.y, sy0); \
                    sx1 = fmaf(M[q].y, c1.x, sx1); sy1 = fmaf(M[q].y, c1.y, sy1); \
                    sx0 = fmaf(M[q].z, c2.x, sx0); sy0 = fmaf(M[q].z, c2.y, sy0); \
                    sx1 = fmaf(M[q].w, c3.x, sx1); sy1 = fmaf(M[q].w, c3.y, sy1); \
                }                                                            \
                float2 xk = xsh[HALFS + (K)];                                \
                float p1 = fmaf(xk.x, sx0 + sx1, xk.y * (sy0 + sy1));        \
                float oth = __shfl_xor_sync(0xffffffffu, p1, 16);            \
                if (wr) lvsm[144 + ((PAR) ^ 1) * 72 + sto] = p1 + oth;       \
            }                                                                \
            /* ---------- C prefetch AFTER STS: hides sync skew ---------- */\
            if ((K) < HALFS - 1) {                                           \
                const float2* Ns = ring + slotn * SLAB + coff;               \
                _Pragma("unroll")                                            \
                for (int i = 0; i < 32; i++) NXT[i] = Ns[i * 64];            \
            }                                                                \
            slotn = (slotn == RING - 1) ? 0 : slotn + 1;                     \
            __syncthreads();                                                 \
        }

#pragma unroll 1
        for (int k = 0; k < HALFS; k += 2) {
            WSTEP(A, B, k, 0);
            WSTEP(B, A, k + 1, 1);
        }
#undef WSTEP

        if (t < 64) {        // final lv in buffer 0 (98 even)
            int h = t >> 5, p = t & 31;
            float v0 = lvsm[h * 36 + p];
            float v1 = lvsm[144 + h * 36 + p];
            if (half == 0) { g_vecL[b0][t] = v0; g_vecL[b0 + 1][t] = v1; }
            else           { g_vecR[b0][t] = v0; g_vecR[b0 + 1][t] = v1; }
        }
    } else {
        // ============================ TMA warp ============================
#pragma unroll 1
        for (int k = 0; k < HALFS; k++) {
            if (lane == 0 && k + 2 < HALFS)     // certify slab k+2
                mbar_wait(fb + 8 * ((k + 2) % RING), ((k + 2) / RING) & 1);
            __syncthreads();
            if (lane == 0 && k + RING < HALFS) {   // refill slot k%RING
                mbar_expect_tx(fb + 8 * (k % RING), SLAB_BYTES);
                bulk_g2s(ru + (k % RING) * SLAB_BYTES,
                         s0 + (long)(k + RING) * sstride,
                         SLAB_BYTES, fb + 8 * (k % RING));
            }
        }
    }
}

// ---------------------------------------------------------------------------
// Kernel 3: 640 CTAs, CTA = (b, o): out[b,o] = sum_{l,r} L[b,l] oc[o,l,r] R[b,r]
// ---------------------------------------------------------------------------
__global__ __launch_bounds__(64) void out_kernel(const float* __restrict__ oc,
                                                 float* __restrict__ out)
{
    const int bo = blockIdx.x;
    const int b  = bo / OO;
    const int o  = bo - b * OO;
    const int r  = threadIdx.x;
    __shared__ float Ls[64];
    __shared__ float red[2];

    Ls[r] = g_vecL[b][r];
    const float R = g_vecR[b][r];
    __syncthreads();

    float acc = 0.f;
    const float* m = oc + o * 4096 + r;
#pragma unroll 16
    for (int l = 0; l < 64; l++) acc = fmaf(Ls[l], m[l * 64], acc);
    acc *= R;
#pragma unroll
    for (int off = 16; off; off >>= 1)
        acc += __shfl_down_sync(0xffffffffu, acc, off);
    if ((r & 31) == 0) red[r >> 5] = acc;
    __syncthreads();
    if (r == 0) out[b * OO + o] = red[0] + red[1];
}

// ---------------------------------------------------------------------------
extern "C" void kernel_launch(void* const* d_in, const int* in_sizes, int n_in,
                              void* d_out, int out_size)
{
    const float* x = nullptr;
    const float* cores = nullptr;
    const float* oc = nullptr;
    for (int i = 0; i < n_in; i++) {
        if (in_sizes[i] == BB * SS * 2)         x = (const float*)d_in[i];
        else if (in_sizes[i] == SS * SLAB * 2)  cores = (const float*)d_in[i];
        else if (in_sizes[i] == OO * 4096)      oc = (const float*)d_in[i];
    }

    const int DYN_SMEM = RING * SLAB_BYTES + 1152 + 1568 + 64;
    cudaFuncSetAttribute(chain_kernel, cudaFuncAttributeMaxDynamicSharedMemorySize, DYN_SMEM);

    transpose_kernel<<<4 * (SS - HALFS), 128>>>((const float2*)cores);
    chain_kernel<<<64, NT, DYN_SMEM>>>(x, (const float2*)cores);
    out_kernel<<<BB * OO, 64>>>(oc, (float*)d_out);
}